// round 9
// baseline (speedup 1.0000x reference)
#include <cuda_runtime.h>
#include <cstdint>

typedef unsigned long long ull;

#define NB 128
#define NT 256
#define CLS 16
#define TT 2048
#define FF 128
#define HH 256
#define SLOT (32*HH)
#define MEMOFF ((TT+1)*SLOT)

// shared float offsets
#define O_SD   0        // sabd[384][8]  (x|h), batch values duplicated
#define O_CD0  3072     // c dup buffer A [256][8]
#define O_CD1  5120     // c dup buffer B [256][8]
#define O_WP   7168     // WPp[k][16][2] = (Wci, Wcf)
#define O_WO   15360    // WOp[k][8][2]  = (Wco[pp], Wco[pp+8])
#define O_PA   19456    // PA[8][128 ull]
#define O_PP   21504    // PP[8][64 ull]
#define O_PO   22528    // PO[8][32 ull]
#define O_BAP  23040    // bap[32 ull]
#define O_BPP  23104    // bpp[16 ull]
#define O_BOP  23136    // bop[8 ull]
#define O_CNS  23152    // scratch [64]
#define O_YOS  23216    // o preact scratch [64]
#define O_MB   23280    // mbar_c (ull), mbar_h (ull)
#define SMF    23288
#define SMB    (SMF*4)

__device__ __forceinline__ float sgm(float v){ return 1.f/(1.f+__expf(-v)); }
__device__ __forceinline__ float th(float v){ return 2.f/(1.f+__expf(-2.f*v)) - 1.f; }

__device__ __forceinline__ ull pk(float lo, float hi){
  ull r; asm("mov.b64 %0, {%1,%2};" : "=l"(r) : "f"(lo), "f"(hi)); return r;
}
__device__ __forceinline__ void upk(float& lo, float& hi, ull v){
  asm("mov.b64 {%0,%1}, %2;" : "=f"(lo), "=f"(hi) : "l"(v));
}
#define FMA2(d,a,b) asm("fma.rn.f32x2 %0, %1, %2, %0;" : "+l"(d) : "l"(a), "l"(b))
#define ADD2(d,a,b) asm("add.rn.f32x2 %0, %1, %2;" : "=l"(d) : "l"(a), "l"(b))

__device__ __forceinline__ uint32_t s2u(const void* p){
  uint32_t a;
  asm("{ .reg .u64 t; cvta.to.shared.u64 t, %1; cvt.u32.u64 %0, t; }" : "=r"(a) : "l"(p));
  return a;
}
__device__ __forceinline__ void stc64(uint32_t la, uint32_t rk, ull v){
  uint32_t ra;
  asm("mapa.shared::cluster.u32 %0, %1, %2;" : "=r"(ra) : "r"(la), "r"(rk));
  asm volatile("st.shared::cluster.b64 [%0], %1;" :: "r"(ra), "l"(v) : "memory");
}
// release-arrive on peer rk's mbarrier (cumulative release covers syncthreads-ordered stores)
__device__ __forceinline__ void marrive(uint32_t la, uint32_t rk){
  uint32_t ra;
  asm("mapa.shared::cluster.u32 %0, %1, %2;" : "=r"(ra) : "r"(la), "r"(rk));
  asm volatile("mbarrier.arrive.release.cluster.shared::cluster.b64 _, [%0];" :: "r"(ra) : "memory");
}
__device__ __forceinline__ void mwait(uint32_t la, uint32_t parity){
  uint32_t done;
  do {
    asm volatile("{\n\t.reg .pred p;\n\t"
      "mbarrier.try_wait.parity.acquire.cluster.shared::cta.b64 p, [%1], %2, 0x989680;\n\t"
      "selp.b32 %0,1,0,p;\n\t}"
      : "=r"(done) : "r"(la), "r"(parity) : "memory");
  } while(!done);
}
#define CARRIVE() asm volatile("barrier.cluster.arrive.aligned;" ::: "memory")
#define CWAIT()   asm volatile("barrier.cluster.wait.aligned;"   ::: "memory")
#define ULL(off) (*(ull*)&sm[off])

__global__ void zk(float* __restrict__ out){
  int i = blockIdx.x*blockDim.x + threadIdx.x;
  if (i < SLOT){ out[i]=0.f; out[MEMOFF+i]=0.f; }   // h0 = c0 = 0
}

__global__ void __launch_bounds__(NT,1) __cluster_dims__(CLS,1,1) lstm(
  const float* __restrict__ x,  const float* __restrict__ Wx,  const float* __restrict__ bx,
  const float* __restrict__ Wh, const float* __restrict__ bh,
  const float* __restrict__ Wci,const float* __restrict__ bci,
  const float* __restrict__ Wcf,const float* __restrict__ bcf,
  const float* __restrict__ Wco,const float* __restrict__ bco,
  float* __restrict__ out)
{
  extern __shared__ float sm[];
  const int tid = threadIdx.x, warp = tid>>5, lane = tid&31;
  uint32_t rank; asm("mov.u32 %0, %%cluster_ctarank;" : "=r"(rank));
  const int u0 = (int)rank*16;
  const int b0 = (blockIdx.x>>4)*4;
  const uint32_t sbase = s2u(sm);
  const uint32_t mbc = sbase + O_MB*4u;
  const uint32_t mbh = sbase + O_MB*4u + 8u;

  // ---- register-resident main weights ----
  int uu_p = (lane<16)? lane : lane-16;
  int glo  = (lane<16)? (u0+uu_p)     : (256+u0+uu_p);
  int ghi  = (lane<16)? (512+u0+uu_p) : (768+u0+uu_p);
  ull wpr_[48];
  #pragma unroll
  for (int kk=0; kk<48; kk++){
    int k = warp*48 + kk;
    float wlo = (k<FF)? Wx[glo*FF+k] : Wh[glo*HH+(k-FF)];
    float whi = (k<FF)? Wx[ghi*FF+k] : Wh[ghi*HH+(k-FF)];
    wpr_[kk] = pk(wlo, whi);
  }

  for (int i=tid; i<4096; i+=NT){
    int k=i>>4, uu=i&15;
    sm[O_WP + i*2    ] = Wci[(u0+uu)*HH+k];
    sm[O_WP + i*2 + 1] = Wcf[(u0+uu)*HH+k];
  }
  for (int i=tid; i<2048; i+=NT){
    int k=i>>3, pp=i&7;
    sm[O_WO + i*2    ] = Wco[(u0+pp)*HH+k];
    sm[O_WO + i*2 + 1] = Wco[(u0+pp+8)*HH+k];
  }
  if (tid<32){
    int p=tid, uu=(p<16)?p:p-16;
    int gl=(p<16)?(u0+uu):(256+u0+uu), gh=(p<16)?(512+u0+uu):(768+u0+uu);
    ULL(O_BAP + p*2) = pk(bx[gl]+bh[gl], bx[gh]+bh[gh]);
  } else if (tid<48){
    int uu=tid-32; ULL(O_BPP + uu*2) = pk(bci[u0+uu], bcf[u0+uu]);
  } else if (tid<56){
    int pp=tid-48; ULL(O_BOP + pp*2) = pk(bco[u0+pp], bco[u0+pp+8]);
  }

  for (int i=tid; i<2048; i+=NT) sm[O_SD + 128*8 + i] = 0.f;
  for (int i=tid; i<2048; i+=NT) sm[O_CD0 + i] = 0.f;

  #pragma unroll
  for (int rep=0; rep<2; rep++){
    int it = tid + rep*NT, k = it>>2, b = it&3;
    float v = x[((long)(b0+b)*TT + 0)*FF + k];
    ULL(O_SD + k*8 + b*2) = pk(v,v);
  }
  if (tid==0){
    asm volatile("mbarrier.init.shared.b64 [%0], %1;" :: "r"(mbc), "r"(CLS) : "memory");
    asm volatile("mbarrier.init.shared.b64 [%0], %1;" :: "r"(mbh), "r"(CLS) : "memory");
  }

  __syncthreads();
  CARRIVE(); CWAIT();   // init visible cluster-wide before any push/arrive

  float* hid = out;
  float* mem = out + MEMOFF;

  for (int s=0; s<TT; s++){
    const int cdO = (s&1) ? O_CD1 : O_CD0;
    const int cdN = (s&1) ? O_CD0 : O_CD1;

    // wait for all h(s) pushes (round s-1): parity (s-1)&1
    if (s>0) mwait(mbh, (unsigned)((s-1)&1));

    // prefetch x(s+1)
    float xr0=0.f, xr1=0.f;
    if (s+1<TT){
      int i0=tid, i1=tid+NT;
      xr0 = x[((long)(b0+(i0&3))*TT + (s+1))*FF + (i0>>2)];
      xr1 = x[((long)(b0+(i1&3))*TT + (s+1))*FF + (i1>>2)];
    }

    // ---- phase A: K=384, FFMA2, reg weights ----
    ull a0=0, a1=0, a2=0, a3=0;
    {
      const float* base = sm + O_SD + warp*48*8;
      #pragma unroll
      for (int kk=0; kk<48; kk++){
        const float* q = base + kk*8;
        ulonglong2 sA = *(const ulonglong2*)q;
        ulonglong2 sB = *(const ulonglong2*)(q+4);
        FMA2(a0, wpr_[kk], sA.x); FMA2(a1, wpr_[kk], sA.y);
        FMA2(a2, wpr_[kk], sB.x); FMA2(a3, wpr_[kk], sB.y);
      }
    }
    {
      ulonglong2* d = (ulonglong2*)&sm[O_PA + (warp*128 + lane*4)*2];
      d[0] = make_ulonglong2(a0,a1); d[1] = make_ulonglong2(a2,a3);
    }

    // ---- peepholes i/f over c(s) ----
    {
      int uu = lane&15, bh2 = lane>>4;
      ull p0=0, p1=0;
      const int kb = warp*32;
      #pragma unroll
      for (int kk=0; kk<32; kk++){
        int k = kb+kk;
        ull w = ULL(O_WP + (k*16+uu)*2);
        ulonglong2 cc = *(const ulonglong2*)&sm[cdO + k*8 + bh2*4];
        FMA2(p0, w, cc.x); FMA2(p1, w, cc.y);
      }
      *(ulonglong2*)&sm[O_PP + (warp*64 + uu*4 + bh2*2)*2] = make_ulonglong2(p0,p1);
    }
    __syncthreads();

    // stage x(s+1) (local region; local reads finished at the sync above)
    if (s+1<TT){
      int i0=tid, i1=tid+NT;
      ULL(O_SD + (i0>>2)*8 + (i0&3)*2) = pk(xr0,xr0);
      ULL(O_SD + (i1>>2)*8 + (i1&3)*2) = pk(xr1,xr1);
    }

    // ---- gates + reduces (tid<64) ----
    if (tid<64){
      int uu = tid>>2, b = tid&3;
      ull v0 = ULL(O_BAP + uu*2);
      ull v1 = ULL(O_BAP + (16+uu)*2);
      ull vp = ULL(O_BPP + uu*2);
      #pragma unroll
      for (int w=0; w<8; w++){
        ADD2(v0, v0, ULL(O_PA + (w*128 + uu*4      + b)*2));
        ADD2(v1, v1, ULL(O_PA + (w*128 + (16+uu)*4 + b)*2));
        ADD2(vp, vp, ULL(O_PP + (w*64  + uu*4      + b)*2));
      }
      float yi,yo,yf,yg,pi,pf;
      upk(yi,yo,v0); upk(yf,yg,v1); upk(pi,pf,vp);
      float co = sm[cdO + (u0+uu)*8 + b*2];
      float cn = sgm(yf+pf)*co + sgm(yi+pi)*th(yg);
      mem[(long)(s+1)*SLOT + (long)(b0+b)*HH + u0+uu] = cn;
      sm[O_CNS + tid] = cn;
      sm[O_YOS + tid] = yo;
    }
    __syncthreads();

    // ---- push c_new to all 16 CTAs: thread -> peer r=tid>>4, 4 values ----
    {
      uint32_t r = (uint32_t)(tid>>4);
      int q = tid&15;
      #pragma unroll
      for (int j=0; j<4; j++){
        float v = sm[O_CNS + q*4 + j];
        stc64(sbase + (uint32_t)(cdN + (u0+q)*8 + j*2)*4u, r, pk(v,v));
      }
    }
    __syncthreads();
    if (tid<16) marrive(mbc, (uint32_t)tid);
    mwait(mbc, (unsigned)(s&1));   // all c_new(s+1) visible

    // ---- phase B: o-peephole over c_new ----
    {
      int pp = lane&7, bb = lane>>3;
      ull ab = 0;
      const int kb = warp*32;
      #pragma unroll
      for (int kk=0; kk<32; kk++){
        int k = kb+kk;
        ull w = ULL(O_WO + (k*8+pp)*2);
        ull c = ULL(cdN + k*8 + bb*2);
        FMA2(ab, w, c);
      }
      ULL(O_PO + (warp*32 + pp*4 + bb)*2) = ab;
    }
    __syncthreads();

    // ---- o gate + h_new (tid<32) ----
    if (tid<32){
      int pp = tid>>2, b = tid&3;
      ull v = ULL(O_BOP + pp*2);
      #pragma unroll
      for (int w=0; w<8; w++) ADD2(v, v, ULL(O_PO + (w*32 + tid)*2));
      float vlo, vhi; upk(vlo, vhi, v);
      #pragma unroll
      for (int e=0; e<2; e++){
        int uu = pp + 8*e;
        float y  = sm[O_YOS + uu*4 + b] + (e ? vhi : vlo);
        float cn = sm[cdN + (u0+uu)*8 + b*2];
        float hn = sgm(y) * th(cn);
        hid[(long)(s+1)*SLOT + (long)(b0+b)*HH + u0+uu] = hn;
        sm[O_CNS + uu*4 + b] = hn;
      }
    }
    __syncthreads();

    // ---- push h_new to all CTAs' sabd h-region ----
    {
      uint32_t r = (uint32_t)(tid>>4);
      int q = tid&15;
      #pragma unroll
      for (int j=0; j<4; j++){
        float v = sm[O_CNS + q*4 + j];
        stc64(sbase + (uint32_t)(O_SD + (FF+u0+q)*8 + j*2)*4u, r, pk(v,v));
      }
    }
    __syncthreads();
    if (tid<16) marrive(mbh, (uint32_t)tid);
    // wait happens at top of next step
  }

  // EXIT FENCE: no CTA may return while peers still have in-flight
  // st.shared::cluster / mbarrier.arrive targeting this CTA's smem.
  // cluster.arrive has release semantics over all prior cluster stores.
  CARRIVE(); CWAIT();
}

extern "C" void kernel_launch(void* const* d_in, const int* in_sizes, int n_in,
                              void* d_out, int out_size) {
  cudaFuncSetAttribute(lstm, cudaFuncAttributeMaxDynamicSharedMemorySize, SMB);
  cudaFuncSetAttribute(lstm, cudaFuncAttributeNonPortableClusterSizeAllowed, 1);
  float* out = (float*)d_out;
  zk<<<32, 256>>>(out);
  lstm<<<NB, NT, SMB>>>(
    (const float*)d_in[0], (const float*)d_in[1], (const float*)d_in[2],
    (const float*)d_in[3], (const float*)d_in[4],
    (const float*)d_in[5], (const float*)d_in[6],
    (const float*)d_in[7], (const float*)d_in[8],
    (const float*)d_in[9], (const float*)d_in[10],
    out);
}

// round 10
// speedup vs baseline: 1.1645x; 1.1645x over previous
#include <cuda_runtime.h>
#include <cstdint>

#define NB 128
#define NT 256
#define TT 2048
#define FF 128
#define HH 256
#define SLOT (32*HH)
#define MEMOFF ((TT+1)*SLOT)

// shared float offsets
#define O_SA0 0                    // sa0[16][385]  x|h group 0
#define O_SA1 6160                 // sa1[16][385]
#define O_CB0 12320                // cb0[16][257]  c vector group 0
#define O_CB1 16432                // cb1[16][257]
#define O_WA  20544                // WA[384][8]   r=u*4+q
#define O_WP  23616                // WP[256][4]   r=u*2+p
#define O_WO  24640                // WO[256][2]
#define O_PA  25152                // PA[8][8][16]
#define O_PP  26176                // PP[8][4][16]
#define O_PO  26688                // PO[8][2][16]
#define O_YA  26944                // YA[8][16]
#define O_YP  27072                // YP[4][16]
#define O_YO0 27136                // yo scratch g0 [32]
#define O_YO1 27168                // yo scratch g1 [32]
#define O_BA  27200                // ba[8]
#define O_BP  27208                // bp[4]
#define O_BO  27212                // bo[2] (pad 4)
#define SMF   27216
#define SMB   (SMF*4)

__device__ unsigned g_ctr[128];    // counters at 0(c0), 32(c1), 64(h0), 96(h1)

__device__ __forceinline__ float sgm(float v){ return 1.f/(1.f+__expf(-v)); }
__device__ __forceinline__ float th(float v){ return 2.f/(1.f+__expf(-2.f*v)) - 1.f; }

__device__ __forceinline__ void garrive(unsigned* c){
  __syncthreads();                       // all STGs of this phase done
  if (threadIdx.x==0){ __threadfence(); atomicAdd(c,1u); }
}
__device__ __forceinline__ void gwait(unsigned* c, unsigned tgt){
  if (threadIdx.x==0){
    unsigned v;
    do { asm volatile("ld.acquire.gpu.u32 %0,[%1];" : "=r"(v) : "l"(c) : "memory"); } while (v < tgt);
  }
  __syncthreads();
}

__global__ void zk(float* __restrict__ out){
  int i = blockIdx.x*blockDim.x + threadIdx.x;
  if (i < 128) g_ctr[i] = 0u;
  if (i < SLOT){ out[i]=0.f; out[MEMOFF+i]=0.f; }   // h0 = c0 = 0
}

// ---- group phase A: stage x,h; gate GEMM + i/f peepholes; reduce; gates; write c_new ----
__device__ __forceinline__ void groupA(float* sm,
    const float* __restrict__ x, const float* __restrict__ hid, float* __restrict__ mem,
    int s, int gb, int saO, int cbO, int yoO, int j0, int tid, int warp, int lane)
{
  // stage x(s): 16b x 32 f4
  #pragma unroll
  for (int it=0; it<2; it++){
    int idx = tid + it*NT, b = idx>>5, f = idx&31;
    float4 v = *(const float4*)(x + ((long)(gb+b)*TT + s)*FF + f*4);
    float* d = sm + saO + b*385 + f*4;
    d[0]=v.x; d[1]=v.y; d[2]=v.z; d[3]=v.w;
  }
  // stage h(s): 16b x 64 f4
  #pragma unroll
  for (int it=0; it<4; it++){
    int idx = tid + it*NT, b = idx>>6, f = idx&63;
    float4 v = *(const float4*)(hid + (long)s*SLOT + (long)(gb+b)*HH + f*4);
    float* d = sm + saO + b*385 + FF + f*4;
    d[0]=v.x; d[1]=v.y; d[2]=v.z; d[3]=v.w;
  }
  __syncthreads();

  // phase A: lane = b(16) + 16*rh; rows rh*4..rh*4+3; k = warp*48..+47
  {
    int b = lane&15, rh = lane>>4;
    float a0=0,a1=0,a2=0,a3=0;
    const float* sa = sm + saO + b*385;
    #pragma unroll 8
    for (int kk=0; kk<48; kk++){
      int k = warp*48 + kk;
      float sv = sa[k];
      float4 w = *(float4*)&sm[O_WA + k*8 + rh*4];
      a0 += w.x*sv; a1 += w.y*sv; a2 += w.z*sv; a3 += w.w*sv;
    }
    sm[O_PA + warp*128 + (rh*4+0)*16 + b] = a0;
    sm[O_PA + warp*128 + (rh*4+1)*16 + b] = a1;
    sm[O_PA + warp*128 + (rh*4+2)*16 + b] = a2;
    sm[O_PA + warp*128 + (rh*4+3)*16 + b] = a3;
  }
  // peepholes i,f over old c: lane = b + 16*rh2; rows rh2*2..+1; k = warp*32..+31
  {
    int b = lane&15, rh2 = lane>>4;
    float p0=0, p1=0;
    const float* cbp = sm + cbO + b*257;
    #pragma unroll 8
    for (int kk=0; kk<32; kk++){
      int k = warp*32 + kk;
      float cv = cbp[k];
      float2 w = *(float2*)&sm[O_WP + k*4 + rh2*2];
      p0 += w.x*cv; p1 += w.y*cv;
    }
    sm[O_PP + warp*64 + (rh2*2+0)*16 + b] = p0;
    sm[O_PP + warp*64 + (rh2*2+1)*16 + b] = p1;
  }
  __syncthreads();

  // cross-warp reduce
  if (tid < 128){
    int r = tid>>4, b = tid&15;
    float v = sm[O_BA + r];
    #pragma unroll
    for (int w=0; w<8; w++) v += sm[O_PA + w*128 + r*16 + b];
    sm[O_YA + r*16 + b] = v;
  } else if (tid < 192){
    int t = tid-128, r = t>>4, b = t&15;
    float v = sm[O_BP + r];
    #pragma unroll
    for (int w=0; w<8; w++) v += sm[O_PP + w*64 + r*16 + b];
    sm[O_YP + r*16 + b] = v;
  }
  __syncthreads();

  // gates + c_new (32 threads: u=tid>>4, b=tid&15)
  if (tid < 32){
    int u = tid>>4, b = tid&15;
    float yi = sm[O_YA + (u*4+0)*16 + b] + sm[O_YP + (u*2+0)*16 + b];
    float yf = sm[O_YA + (u*4+1)*16 + b] + sm[O_YP + (u*2+1)*16 + b];
    float yg = sm[O_YA + (u*4+3)*16 + b];
    float co = sm[cbO + b*257 + j0 + u];
    float cn = sgm(yf)*co + sgm(yi)*th(yg);
    mem[(long)(s+1)*SLOT + (long)(gb+b)*HH + j0+u] = cn;
    sm[yoO + tid] = sm[O_YA + (u*4+2)*16 + b];
  }
}

// ---- group phase B: stage c_new; o-peephole; h_new ----
__device__ __forceinline__ void groupB(float* sm,
    float* __restrict__ hid, const float* __restrict__ mem,
    int s, int gb, int cbO, int yoO, int j0, int tid, int warp, int lane)
{
  // stage c(s+1): 16b x 64 f4 (overwrites old c — consumers all done)
  #pragma unroll
  for (int it=0; it<4; it++){
    int idx = tid + it*NT, b = idx>>6, f = idx&63;
    float4 v = *(const float4*)(mem + (long)(s+1)*SLOT + (long)(gb+b)*HH + f*4);
    float* d = sm + cbO + b*257 + f*4;
    d[0]=v.x; d[1]=v.y; d[2]=v.z; d[3]=v.w;
  }
  __syncthreads();

  // o-peephole: lane = b + 16*u; k = warp*32..+31
  {
    int b = lane&15, u = lane>>4;
    float q0 = 0.f;
    const float* cbp = sm + cbO + b*257;
    #pragma unroll 8
    for (int kk=0; kk<32; kk++){
      int k = warp*32 + kk;
      q0 += sm[O_WO + k*2 + u] * cbp[k];
    }
    sm[O_PO + warp*32 + u*16 + b] = q0;
  }
  __syncthreads();

  if (tid < 32){
    int u = tid>>4, b = tid&15;
    float v = sm[O_BO + u] + sm[yoO + tid];
    #pragma unroll
    for (int w=0; w<8; w++) v += sm[O_PO + w*32 + u*16 + b];
    float cn = sm[cbO + b*257 + j0+u];
    float hn = sgm(v)*th(cn);
    hid[(long)(s+1)*SLOT + (long)(gb+b)*HH + j0+u] = hn;
  }
}

__global__ void __launch_bounds__(NT,1) lstm(
  const float* __restrict__ x,  const float* __restrict__ Wx,  const float* __restrict__ bx,
  const float* __restrict__ Wh, const float* __restrict__ bh,
  const float* __restrict__ Wci,const float* __restrict__ bci,
  const float* __restrict__ Wcf,const float* __restrict__ bcf,
  const float* __restrict__ Wco,const float* __restrict__ bco,
  float* __restrict__ out)
{
  extern __shared__ float sm[];
  const int tid = threadIdx.x, warp = tid>>5, lane = tid&31;
  const int j0 = blockIdx.x*2;

  // ---- one-time weight staging ----
  for (int i=tid; i<384*8; i+=NT){
    int k=i>>3, r=i&7, u=r>>2, q=r&3, g=q*HH+j0+u;
    sm[O_WA+i] = (k<FF) ? Wx[g*FF+k] : Wh[g*HH+k-FF];
  }
  for (int i=tid; i<256*4; i+=NT){
    int k=i>>2, r=i&3, u=r>>1, p=r&1;
    sm[O_WP+i] = (p?Wcf:Wci)[(j0+u)*HH+k];
  }
  for (int i=tid; i<256*2; i+=NT){
    int k=i>>1, u=i&1; sm[O_WO+i] = Wco[(j0+u)*HH+k];
  }
  if (tid<8){ int u=tid>>2,q=tid&3,g=q*HH+j0+u; sm[O_BA+tid]=bx[g]+bh[g]; }
  else if (tid<12){ int r=tid-8,u=r>>1; sm[O_BP+r]=((r&1)?bcf:bci)[j0+u]; }
  else if (tid<14){ sm[O_BO+tid-12]=bco[j0+tid-12]; }

  // c0 = 0 in both c buffers
  for (int i=tid; i<16*257; i+=NT){ sm[O_CB0+i]=0.f; sm[O_CB1+i]=0.f; }
  __syncthreads();

  float* hid = out;
  float* mem = out + MEMOFF;

  for (int s=0; s<TT; s++){
    unsigned tgt = (unsigned)(s+1)*NB;

    if (s>0) gwait(&g_ctr[64], (unsigned)s*NB);            // h0(s) ready
    groupA(sm, x, hid, mem, s, 0,  O_SA0, O_CB0, O_YO0, j0, tid, warp, lane);
    garrive(&g_ctr[0]);                                     // c0 pushed

    if (s>0) gwait(&g_ctr[96], (unsigned)s*NB);            // h1(s) ready
    groupA(sm, x, hid, mem, s, 16, O_SA1, O_CB1, O_YO1, j0, tid, warp, lane);
    garrive(&g_ctr[32]);                                    // c1 pushed

    gwait(&g_ctr[0], tgt);                                  // c0 complete (covered by A1)
    groupB(sm, hid, mem, s, 0,  O_CB0, O_YO0, j0, tid, warp, lane);
    garrive(&g_ctr[64]);                                    // h0 pushed

    gwait(&g_ctr[32], tgt);                                 // c1 complete (covered by B0)
    groupB(sm, hid, mem, s, 16, O_CB1, O_YO1, j0, tid, warp, lane);
    garrive(&g_ctr[96]);                                    // h1 pushed
  }
}

extern "C" void kernel_launch(void* const* d_in, const int* in_sizes, int n_in,
                              void* d_out, int out_size) {
  cudaFuncSetAttribute(lstm, cudaFuncAttributeMaxDynamicSharedMemorySize, SMB);
  float* out = (float*)d_out;
  zk<<<32, 256>>>(out);
  lstm<<<NB, NT, SMB>>>(
    (const float*)d_in[0], (const float*)d_in[1], (const float*)d_in[2],
    (const float*)d_in[3], (const float*)d_in[4],
    (const float*)d_in[5], (const float*)d_in[6],
    (const float*)d_in[7], (const float*)d_in[8],
    (const float*)d_in[9], (const float*)d_in[10],
    out);
}